// round 7
// baseline (speedup 1.0000x reference)
#include <cuda_runtime.h>

#define NG   2048
#define NB   4
#define CIN  16
#define COUT 32
#define NCTX 256
#define NOUT 1024

#define TPB   512
#define NWARP 16
#define TGT   4                    // targets per warp
#define TGT_BLK 32                 // 8 target-groups * 4 targets
#define KP    (CIN / 2)            // 8 channel pairs
#define KQ    (CIN / 4)            // 4 channel quads (ulonglong2 elements)
#define HALFPTS (NG / 2)           // grid points per warp-half
#define NIT   (HALFPTS / 32)       // 32 inner iterations per warp

__device__ __forceinline__ float ex2(float x) {
    float y;
    asm("ex2.approx.ftz.f32 %0, %1;" : "=f"(y) : "f"(x));
    return y;
}
__device__ __forceinline__ unsigned long long pack2(float lo, float hi) {
    unsigned long long v;
    asm("mov.b64 %0, {%1, %2};" : "=l"(v) : "f"(lo), "f"(hi));
    return v;
}
__device__ __forceinline__ void unpack2(unsigned long long v, float& lo, float& hi) {
    asm("mov.b64 {%0, %1}, %2;" : "=f"(lo), "=f"(hi) : "l"(v));
}
__device__ __forceinline__ void fma2(unsigned long long& d, unsigned long long a, unsigned long long b) {
    asm("fma.rn.f32x2 %0, %1, %2, %0;" : "+l"(d) : "l"(a), "l"(b));
}
__device__ __forceinline__ void add2(unsigned long long& d, unsigned long long a) {
    asm("add.rn.f32x2 %0, %0, %1;" : "+l"(d) : "l"(a));
}
// Element swizzle for the 16B-element layout. Conflict-free for:
//  - staging STS.128 (lanes write elements at stride 4)
//  - mainloop LDS.128 (lanes read consecutive elements)
__device__ __forceinline__ int eswz(int e) { return e ^ ((e >> 3) & 7); }

extern __shared__ ulonglong2 s_r4[];   // [KQ][NG] 16B elems = 128 KB (+W after)

__global__ __launch_bounds__(TPB, 1)
void conv_decoder_fused(const float* __restrict__ r,
                        const float* __restrict__ xc,
                        const float* __restrict__ xt,
                        const float* __restrict__ sigma,
                        const float* __restrict__ W,
                        const float* __restrict__ bias,
                        float* __restrict__ out) {
    ulonglong2* r4_s = s_r4;                          // [KQ][NG]
    float* W_s = (float*)(s_r4 + KQ * NG);            // CIN*COUT

    __shared__ float s_mn[NWARP], s_mx[NWARP], s_sq[CIN];
    __shared__ float s_red[TGT_BLK][COUT];            // half-1 projected partials

    const int b    = blockIdx.y;
    const int tid  = threadIdx.x;
    const int warp = tid >> 5;
    const int lane = tid & 31;
    const int wt   = warp & 7;       // target-group within block
    const int hs   = warp >> 3;      // grid half this warp sums

    // ---- Phase A: prep + staging (one __syncthreads) ---------------------
    {
        float mn = 1e30f, mx = -1e30f;
        for (int i = tid; i < NB * NCTX; i += TPB) {
            float v = xc[i]; mn = fminf(mn, v); mx = fmaxf(mx, v);
        }
        for (int i = tid; i < NB * NOUT; i += TPB) {
            float v = xt[i]; mn = fminf(mn, v); mx = fmaxf(mx, v);
        }
        #pragma unroll
        for (int s = 16; s > 0; s >>= 1) {
            mn = fminf(mn, __shfl_xor_sync(0xFFFFFFFFu, mn, s));
            mx = fmaxf(mx, __shfl_xor_sync(0xFFFFFFFFu, mx, s));
        }
        if (lane == 0) { s_mn[warp] = mn; s_mx[warp] = mx; }
    }
    // exp(-0.5 d^2/s^2) = exp2(-(d*sq)^2),  sq = sqrt(0.5*log2(e)) / s
    if (tid < CIN) s_sq[tid] = 0.84932180028801907f * expf(-sigma[tid]);
    for (int i = tid; i < CIN * COUT; i += TPB) W_s[i] = W[i];
    // Stage r[b] as channel QUADS: element (k2, g) = {pack2(c=4k2, 4k2+1),
    // pack2(4k2+2, 4k2+3)}. 16 LDG.128 + 16 STS.128 per thread.
    {
        const float4* rb4 = (const float4*)(r + (size_t)b * CIN * NG);
        #pragma unroll
        for (int k2 = 0; k2 < KQ; k2++) {
            float4 a = rb4[(4 * k2 + 0) * (NG / 4) + tid];
            float4 c = rb4[(4 * k2 + 1) * (NG / 4) + tid];
            float4 e = rb4[(4 * k2 + 2) * (NG / 4) + tid];
            float4 f = rb4[(4 * k2 + 3) * (NG / 4) + tid];
            float va[4] = {a.x, a.y, a.z, a.w};
            float vc[4] = {c.x, c.y, c.z, c.w};
            float ve[4] = {e.x, e.y, e.z, e.w};
            float vf[4] = {f.x, f.y, f.z, f.w};
            #pragma unroll
            for (int i = 0; i < 4; i++) {
                ulonglong2 el;
                el.x = pack2(va[i], vc[i]);
                el.y = pack2(ve[i], vf[i]);
                r4_s[k2 * NG + eswz(4 * tid + i)] = el;
            }
        }
    }
    __syncthreads();

    float mn = s_mn[0], mx = s_mx[0];
    #pragma unroll
    for (int w = 1; w < NWARP; w++) {
        mn = fminf(mn, s_mn[w]); mx = fmaxf(mx, s_mx[w]);
    }
    const float xmin = mn - 0.1f;
    const float step = (mx + 0.1f - xmin) / (float)(NG - 1);

    bool uniform = true;
    #pragma unroll
    for (int c = 1; c < CIN; c++) uniform &= (s_sq[c] == s_sq[0]);

    const int o0 = blockIdx.x * TGT_BLK + wt * TGT;
    const int gbase = hs * HALFPTS + lane;

    float op[TGT];   // this lane's projected output-channel value per target

    if (uniform) {
        const float sq    = s_sq[0];
        const float stepq = step * sq;
        const float dstep = 32.0f * stepq;

        float d[TGT];
        #pragma unroll
        for (int t = 0; t < TGT; t++)
            d[t] = fmaf((float)gbase, stepq, xmin * sq) - xt[b * NOUT + o0 + t] * sq;

        unsigned long long acc[TGT][KP];
        #pragma unroll
        for (int t = 0; t < TGT; t++)
            #pragma unroll
            for (int k = 0; k < KP; k++) acc[t][k] = 0ull;

        // Software-pipelined ping-pong: prefetch next r quads and compute
        // weights BEFORE each FMA2 wall. Live regs ~118 (no spill at 128 cap).
        int e = gbase;
        ulonglong2 rvA[KQ], rvB[KQ];
        #pragma unroll
        for (int k2 = 0; k2 < KQ; k2++) rvA[k2] = r4_s[k2 * NG + eswz(e)];

        #pragma unroll 1
        for (int it = 0; it < NIT; it += 2) {
            // --- even step: weights, prefetch B, FMA with A ---
            unsigned long long w2[TGT];
            #pragma unroll
            for (int t = 0; t < TGT; t++) {
                float w = ex2(d[t] * -d[t]);
                d[t] += dstep;
                w2[t] = pack2(w, w);
            }
            {
                int en = (e + 32) & (NG - 1);
                #pragma unroll
                for (int k2 = 0; k2 < KQ; k2++) rvB[k2] = r4_s[k2 * NG + eswz(en)];
            }
            #pragma unroll
            for (int t = 0; t < TGT; t++)
                #pragma unroll
                for (int k2 = 0; k2 < KQ; k2++) {
                    fma2(acc[t][2 * k2 + 0], rvA[k2].x, w2[t]);
                    fma2(acc[t][2 * k2 + 1], rvA[k2].y, w2[t]);
                }
            // --- odd step: weights, prefetch A, FMA with B ---
            #pragma unroll
            for (int t = 0; t < TGT; t++) {
                float w = ex2(d[t] * -d[t]);
                d[t] += dstep;
                w2[t] = pack2(w, w);
            }
            {
                int en = (e + 64) & (NG - 1);
                #pragma unroll
                for (int k2 = 0; k2 < KQ; k2++) rvA[k2] = r4_s[k2 * NG + eswz(en)];
            }
            #pragma unroll
            for (int t = 0; t < TGT; t++)
                #pragma unroll
                for (int k2 = 0; k2 < KQ; k2++) {
                    fma2(acc[t][2 * k2 + 0], rvB[k2].x, w2[t]);
                    fma2(acc[t][2 * k2 + 1], rvB[k2].y, w2[t]);
                }
            e += 64;
        }

        // Reduce packed accumulators across lanes first, THEN project.
        #pragma unroll
        for (int s = 16; s > 0; s >>= 1)
            #pragma unroll
            for (int t = 0; t < TGT; t++)
                #pragma unroll
                for (int k = 0; k < KP; k++)
                    add2(acc[t][k], __shfl_xor_sync(0xFFFFFFFFu, acc[t][k], s));

        #pragma unroll
        for (int t = 0; t < TGT; t++) {
            float o = 0.0f;
            #pragma unroll
            for (int k = 0; k < KP; k++) {
                float lo, hi;
                unpack2(acc[t][k], lo, hi);
                o = fmaf(lo, W_s[(2 * k + 0) * COUT + lane], o);
                o = fmaf(hi, W_s[(2 * k + 1) * COUT + lane], o);
            }
            op[t] = o;
        }
    } else {
        // Cold path: per-channel length scales (scalar math).
        float kneg[CIN];
        #pragma unroll
        for (int c = 0; c < CIN; c++) { float s = s_sq[c]; kneg[c] = -(s * s); }

        float xv[TGT];
        #pragma unroll
        for (int t = 0; t < TGT; t++) xv[t] = xt[b * NOUT + o0 + t];

        float acc[TGT][CIN];
        #pragma unroll
        for (int t = 0; t < TGT; t++)
            #pragma unroll
            for (int c = 0; c < CIN; c++) acc[t][c] = 0.0f;

        #pragma unroll 1
        for (int it = 0; it < NIT; it++) {
            int i = gbase + it * 32;
            float gv = fmaf((float)i, step, xmin);
            #pragma unroll
            for (int k2 = 0; k2 < KQ; k2++) {
                ulonglong2 v = r4_s[k2 * NG + eswz(i)];
                float r0, r1, r2, r3;
                unpack2(v.x, r0, r1);
                unpack2(v.y, r2, r3);
                #pragma unroll
                for (int t = 0; t < TGT; t++) {
                    float dd = gv - xv[t];
                    float d2 = dd * dd;
                    acc[t][4 * k2 + 0] = fmaf(r0, ex2(d2 * kneg[4 * k2 + 0]), acc[t][4 * k2 + 0]);
                    acc[t][4 * k2 + 1] = fmaf(r1, ex2(d2 * kneg[4 * k2 + 1]), acc[t][4 * k2 + 1]);
                    acc[t][4 * k2 + 2] = fmaf(r2, ex2(d2 * kneg[4 * k2 + 2]), acc[t][4 * k2 + 2]);
                    acc[t][4 * k2 + 3] = fmaf(r3, ex2(d2 * kneg[4 * k2 + 3]), acc[t][4 * k2 + 3]);
                }
            }
        }
        // Reduce first, then project.
        #pragma unroll
        for (int s = 16; s > 0; s >>= 1)
            #pragma unroll
            for (int t = 0; t < TGT; t++)
                #pragma unroll
                for (int c = 0; c < CIN; c++)
                    acc[t][c] += __shfl_xor_sync(0xFFFFFFFFu, acc[t][c], s);
        #pragma unroll
        for (int t = 0; t < TGT; t++) {
            float o = 0.0f;
            #pragma unroll
            for (int c = 0; c < CIN; c++)
                o = fmaf(acc[t][c], W_s[c * COUT + lane], o);
            op[t] = o;
        }
    }

    // ---- Cross-half combine inside the block -----------------------------
    if (hs == 1) {
        #pragma unroll
        for (int t = 0; t < TGT; t++) s_red[wt * TGT + t][lane] = op[t];
    }
    __syncthreads();
    if (hs == 0) {
        const float bv = bias[lane];
        #pragma unroll
        for (int t = 0; t < TGT; t++)
            out[(size_t)(b * NOUT + o0 + t) * COUT + lane] =
                op[t] + s_red[wt * TGT + t][lane] + bv;
    }
}

extern "C" void kernel_launch(void* const* d_in, const int* in_sizes, int n_in,
                              void* d_out, int out_size) {
    const float* r     = (const float*)d_in[0];
    const float* xc    = (const float*)d_in[1];
    // d_in[2] = y_context — unused by the reference computation.
    const float* xt    = (const float*)d_in[3];
    const float* sigma = (const float*)d_in[4];
    const float* W     = (const float*)d_in[5];
    const float* bias  = (const float*)d_in[6];
    float* out = (float*)d_out;

    (void)in_sizes; (void)n_in; (void)out_size;

    const int smem_bytes = KQ * NG * 16 + CIN * COUT * 4;   // 128KB + 2KB dynamic
    cudaFuncSetAttribute(conv_decoder_fused,
                         cudaFuncAttributeMaxDynamicSharedMemorySize, smem_bytes);

    dim3 grid(NOUT / TGT_BLK, NB);   // (32, 4) = 128 blocks, 1 per SM
    conv_decoder_fused<<<grid, TPB, smem_bytes>>>(r, xc, xt, sigma, W, bias, out);
}

// round 9
// speedup vs baseline: 1.0173x; 1.0173x over previous
#include <cuda_runtime.h>

#define NG   2048
#define NB   4
#define CIN  16
#define COUT 32
#define NCTX 256
#define NOUT 1024

#define TPB   1024
#define NWARP 32
#define TGT   4                    // targets per warp
#define TGT_BLK 32                 // 8 target-groups * 4
#define NIT   32                   // inner iterations (1024 pts / 32 lanes)

__device__ __forceinline__ float ex2(float x) {
    float y;
    asm("ex2.approx.ftz.f32 %0, %1;" : "=f"(y) : "f"(x));
    return y;
}
__device__ __forceinline__ unsigned long long pack2(float lo, float hi) {
    unsigned long long v;
    asm("mov.b64 %0, {%1, %2};" : "=l"(v) : "f"(lo), "f"(hi));
    return v;
}
__device__ __forceinline__ void unpack2(unsigned long long v, float& lo, float& hi) {
    asm("mov.b64 {%0, %1}, %2;" : "=f"(lo), "=f"(hi) : "l"(v));
}
__device__ __forceinline__ void fma2(unsigned long long& d, unsigned long long a, unsigned long long b) {
    asm("fma.rn.f32x2 %0, %1, %2, %0;" : "+l"(d) : "l"(a), "l"(b));
}
__device__ __forceinline__ void add2(unsigned long long& d, unsigned long long a) {
    asm("add.rn.f32x2 %0, %0, %1;" : "+l"(d) : "l"(a));
}
__device__ __forceinline__ unsigned long long shfl_u64(unsigned long long v, int s) {
    return __shfl_xor_sync(0xFFFFFFFFu, v, s);
}

// Layout: element ((g>>5)*4 + quad)*32 + (g&31), 16B elements.
// Mainloop: lanes read consecutive elements -> conflict-free LDS.128,
// per-iter address step = +128 elements (one IADD).
extern __shared__ ulonglong2 s_r4[];   // 8192 elems = 128 KB (+W after)

__global__ __launch_bounds__(TPB, 1)
void conv_decoder_fused(const float* __restrict__ r,
                        const float* __restrict__ xc,
                        const float* __restrict__ xt,
                        const float* __restrict__ sigma,
                        const float* __restrict__ W,
                        const float* __restrict__ bias,
                        float* __restrict__ out) {
    float* W_s = (float*)(s_r4 + 4 * (NG / 32) * 32);   // CIN*COUT after r

    __shared__ float s_mn[NWARP], s_mx[NWARP], s_sq[CIN];
    __shared__ float s_red[3][TGT_BLK][COUT];           // partial buffers

    const int b    = blockIdx.y;
    const int tid  = threadIdx.x;
    const int warp = tid >> 5;
    const int lane = tid & 31;
    const int tg   = warp >> 2;        // target-group 0..7
    const int ch   = (warp >> 1) & 1;  // channel half 0..1
    const int gr   = warp & 1;         // grid half 0..1
    const int role = warp & 3;         // ch*2 + gr

    // ---- Phase A: prep + staging (one __syncthreads) ---------------------
    {
        float mn, mx;
        {   // xc: exactly 1024 values; xt: 4096 = 1 float4 per thread.
            float v = xc[tid];
            mn = v; mx = v;
            float4 t4 = ((const float4*)xt)[tid];
            mn = fminf(mn, fminf(fminf(t4.x, t4.y), fminf(t4.z, t4.w)));
            mx = fmaxf(mx, fmaxf(fmaxf(t4.x, t4.y), fmaxf(t4.z, t4.w)));
        }
        #pragma unroll
        for (int s = 16; s > 0; s >>= 1) {
            mn = fminf(mn, __shfl_xor_sync(0xFFFFFFFFu, mn, s));
            mx = fmaxf(mx, __shfl_xor_sync(0xFFFFFFFFu, mx, s));
        }
        if (lane == 0) { s_mn[warp] = mn; s_mx[warp] = mx; }
    }
    if (tid < CIN) s_sq[tid] = 0.84932180028801907f * expf(-sigma[tid]);
    for (int i = tid; i < CIN * COUT; i += TPB) W_s[i] = W[i];
    // Stage: thread handles g = tid and g = tid+1024. Scalar channel loads
    // (coalesced across lanes), 4 STS.128 per g (conflict-free: idx%8 == lane%8).
    {
        const float* rb = r + (size_t)b * CIN * NG;
        #pragma unroll
        for (int h = 0; h < 2; h++) {
            int g = tid + h * (NG / 2) * 1;   // +1024
            g = tid + h * 1024;
            float v[CIN];
            #pragma unroll
            for (int c = 0; c < CIN; c++) v[c] = rb[c * NG + g];
            int ebase = (g >> 5) * 4 * 32 + (g & 31);
            #pragma unroll
            for (int q = 0; q < 4; q++) {
                ulonglong2 el;
                el.x = pack2(v[4 * q + 0], v[4 * q + 1]);
                el.y = pack2(v[4 * q + 2], v[4 * q + 3]);
                s_r4[ebase + q * 32] = el;
            }
        }
    }
    __syncthreads();

    // Everyone finishes min/max locally via one warp-wide pass.
    float mn = s_mn[lane];
    float mx = s_mx[lane];
    #pragma unroll
    for (int s = 16; s > 0; s >>= 1) {
        mn = fminf(mn, __shfl_xor_sync(0xFFFFFFFFu, mn, s));
        mx = fmaxf(mx, __shfl_xor_sync(0xFFFFFFFFu, mx, s));
    }
    const float xmin = mn - 0.1f;
    const float step = (mx + 0.1f - xmin) / (float)(NG - 1);

    bool uniform = true;
    #pragma unroll
    for (int c = 1; c < CIN; c++) uniform &= (s_sq[c] == s_sq[0]);

    const int o0 = blockIdx.x * TGT_BLK + tg * TGT;
    const int gbase = gr * 1024 + lane;

    float op[TGT];

    if (uniform) {
        const float sq    = s_sq[0];
        const float stepq = step * sq;
        const float dstep = 32.0f * stepq;

        float d[TGT];
        #pragma unroll
        for (int t = 0; t < TGT; t++)
            d[t] = fmaf((float)gbase, stepq, xmin * sq) - xt[b * NOUT + o0 + t] * sq;

        unsigned long long acc[TGT][4];
        #pragma unroll
        for (int t = 0; t < TGT; t++)
            #pragma unroll
            for (int k = 0; k < 4; k++) acc[t][k] = 0ull;

        // Pointer to this warp's first element; +128 elements per iter.
        const ulonglong2* p = s_r4 + (gr * 32) * 128 + ch * 64 + lane;

        #pragma unroll 1
        for (int it = 0; it < NIT; it++) {
            unsigned long long w2[TGT];
            #pragma unroll
            for (int t = 0; t < TGT; t++) {
                float w = ex2(d[t] * -d[t]);
                d[t] += dstep;
                w2[t] = pack2(w, w);
            }
            ulonglong2 rv0 = p[0];
            ulonglong2 rv1 = p[32];
            p += 128;
            #pragma unroll
            for (int t = 0; t < TGT; t++) {
                fma2(acc[t][0], rv0.x, w2[t]);
                fma2(acc[t][1], rv0.y, w2[t]);
                fma2(acc[t][2], rv1.x, w2[t]);
                fma2(acc[t][3], rv1.y, w2[t]);
            }
        }

        // Butterfly-reduce 16 u64 across lanes, then project (lane = cout).
        #pragma unroll
        for (int s = 16; s > 0; s >>= 1)
            #pragma unroll
            for (int t = 0; t < TGT; t++)
                #pragma unroll
                for (int k = 0; k < 4; k++)
                    add2(acc[t][k], shfl_u64(acc[t][k], s));

        const int c0 = ch * 8;   // first channel of this half
        #pragma unroll
        for (int t = 0; t < TGT; t++) {
            float o = 0.0f;
            #pragma unroll
            for (int k = 0; k < 4; k++) {
                float lo, hi;
                unpack2(acc[t][k], lo, hi);
                o = fmaf(lo, W_s[(c0 + 2 * k + 0) * COUT + lane], o);
                o = fmaf(hi, W_s[(c0 + 2 * k + 1) * COUT + lane], o);
            }
            op[t] = o;
        }
    } else {
        // Cold path: per-channel length scales, scalar math on this warp's
        // 8 channels.
        const int c0 = ch * 8;
        float kneg[8];
        #pragma unroll
        for (int c = 0; c < 8; c++) { float s = s_sq[c0 + c]; kneg[c] = -(s * s); }

        float xv[TGT];
        #pragma unroll
        for (int t = 0; t < TGT; t++) xv[t] = xt[b * NOUT + o0 + t];

        float acc[TGT][8];
        #pragma unroll
        for (int t = 0; t < TGT; t++)
            #pragma unroll
            for (int c = 0; c < 8; c++) acc[t][c] = 0.0f;

        const ulonglong2* p = s_r4 + (gr * 32) * 128 + ch * 64 + lane;
        #pragma unroll 1
        for (int it = 0; it < NIT; it++) {
            int g = gbase + it * 32;
            float gv = fmaf((float)g, step, xmin);
            ulonglong2 rv0 = p[0];
            ulonglong2 rv1 = p[32];
            p += 128;
            float rc[8];
            unpack2(rv0.x, rc[0], rc[1]);
            unpack2(rv0.y, rc[2], rc[3]);
            unpack2(rv1.x, rc[4], rc[5]);
            unpack2(rv1.y, rc[6], rc[7]);
            #pragma unroll
            for (int t = 0; t < TGT; t++) {
                float dd = gv - xv[t];
                float d2 = dd * dd;
                #pragma unroll
                for (int c = 0; c < 8; c++)
                    acc[t][c] = fmaf(rc[c], ex2(d2 * kneg[c]), acc[t][c]);
            }
        }
        #pragma unroll
        for (int s = 16; s > 0; s >>= 1)
            #pragma unroll
            for (int t = 0; t < TGT; t++)
                #pragma unroll
                for (int c = 0; c < 8; c++)
                    acc[t][c] += __shfl_xor_sync(0xFFFFFFFFu, acc[t][c], s);
        #pragma unroll
        for (int t = 0; t < TGT; t++) {
            float o = 0.0f;
            #pragma unroll
            for (int c = 0; c < 8; c++)
                o = fmaf(acc[t][c], W_s[(c0 + c) * COUT + lane], o);
            op[t] = o;
        }
    }

    // ---- Combine the 4 contributors (2 ch-halves x 2 grid-halves) --------
    if (role != 0) {
        #pragma unroll
        for (int t = 0; t < TGT; t++)
            s_red[role - 1][tg * TGT + t][lane] = op[t];
    }
    __syncthreads();
    if (role == 0) {
        const float bv = bias[lane];
        #pragma unroll
        for (int t = 0; t < TGT; t++) {
            int row = tg * TGT + t;
            float o = op[t] + s_red[0][row][lane];
            o += s_red[1][row][lane] + s_red[2][row][lane];
            out[(size_t)(b * NOUT + o0 + t) * COUT + lane] = o + bv;
        }
    }
}

extern "C" void kernel_launch(void* const* d_in, const int* in_sizes, int n_in,
                              void* d_out, int out_size) {
    const float* r     = (const float*)d_in[0];
    const float* xc    = (const float*)d_in[1];
    // d_in[2] = y_context — unused by the reference computation.
    const float* xt    = (const float*)d_in[3];
    const float* sigma = (const float*)d_in[4];
    const float* W     = (const float*)d_in[5];
    const float* bias  = (const float*)d_in[6];
    float* out = (float*)d_out;

    (void)in_sizes; (void)n_in; (void)out_size;

    const int smem_bytes = 4 * (NG / 32) * 32 * 16 + CIN * COUT * 4;  // 128KB + 2KB
    cudaFuncSetAttribute(conv_decoder_fused,
                         cudaFuncAttributeMaxDynamicSharedMemorySize, smem_bytes);

    dim3 grid(NOUT / TGT_BLK, NB);   // (32, 4) = 128 blocks, 1 per SM
    conv_decoder_fused<<<grid, TPB, smem_bytes>>>(r, xc, xt, sigma, W, bias, out);
}

// round 10
// speedup vs baseline: 1.1055x; 1.0866x over previous
#include <cuda_runtime.h>

#define NG   2048
#define NB   4
#define CIN  16
#define COUT 32
#define NCTX 256
#define NOUT 1024

#define TPB   1024
#define NWARP 32
#define TGT   4                    // targets per warp
#define TGT_BLK 32                 // 8 target-groups * 4
#define NIT   32                   // inner iterations (1024 pts / 32 lanes)

__device__ __forceinline__ float ex2(float x) {
    float y;
    asm("ex2.approx.ftz.f32 %0, %1;" : "=f"(y) : "f"(x));
    return y;
}
__device__ __forceinline__ unsigned long long pack2(float lo, float hi) {
    unsigned long long v;
    asm("mov.b64 %0, {%1, %2};" : "=l"(v) : "f"(lo), "f"(hi));
    return v;
}
__device__ __forceinline__ void unpack2(unsigned long long v, float& lo, float& hi) {
    asm("mov.b64 {%0, %1}, %2;" : "=f"(lo), "=f"(hi) : "l"(v));
}
__device__ __forceinline__ void fma2(unsigned long long& d, unsigned long long a, unsigned long long b) {
    asm("fma.rn.f32x2 %0, %1, %2, %0;" : "+l"(d) : "l"(a), "l"(b));
}
__device__ __forceinline__ void add2(unsigned long long& d, unsigned long long a) {
    asm("add.rn.f32x2 %0, %0, %1;" : "+l"(d) : "l"(a));
}
__device__ __forceinline__ unsigned long long shfl_u64(unsigned long long v, int s) {
    return __shfl_xor_sync(0xFFFFFFFFu, v, s);
}

// r layout: element ((g>>5)*4 + quad)*32 + (g&31), 16B elements.
extern __shared__ ulonglong2 s_r4[];   // 8192 elems = 128 KB (+W after)

__global__ __launch_bounds__(TPB, 1)
void conv_decoder_fused(const float* __restrict__ r,
                        const float* __restrict__ xc,
                        const float* __restrict__ xt,
                        const float* __restrict__ sigma,
                        const float* __restrict__ W,
                        const float* __restrict__ bias,
                        float* __restrict__ out) {
    float* W_s = (float*)(s_r4 + 4 * (NG / 32) * 32);   // CIN*COUT after r

    __shared__ float s_mn[NWARP], s_mx[NWARP], s_sq[CIN];
    __shared__ unsigned long long sa[NWARP * 128];      // 32 KB group-sum dump
    __shared__ unsigned long long s_z[TGT_BLK * 8];     // 2 KB reduced z pairs

    const int b    = blockIdx.y;
    const int tid  = threadIdx.x;
    const int warp = tid >> 5;
    const int lane = tid & 31;
    const int tg   = warp >> 2;        // target-group 0..7
    const int ch   = (warp >> 1) & 1;  // channel half 0..1
    const int gr   = warp & 1;         // grid half 0..1

    // ---- Phase A: prep + staging (one __syncthreads) ---------------------
    {
        float mn, mx;
        {   // xc: exactly 1024 values; xt: 4096 = 1 float4 per thread.
            float v = xc[tid];
            mn = v; mx = v;
            float4 t4 = ((const float4*)xt)[tid];
            mn = fminf(mn, fminf(fminf(t4.x, t4.y), fminf(t4.z, t4.w)));
            mx = fmaxf(mx, fmaxf(fmaxf(t4.x, t4.y), fmaxf(t4.z, t4.w)));
        }
        #pragma unroll
        for (int s = 16; s > 0; s >>= 1) {
            mn = fminf(mn, __shfl_xor_sync(0xFFFFFFFFu, mn, s));
            mx = fmaxf(mx, __shfl_xor_sync(0xFFFFFFFFu, mx, s));
        }
        if (lane == 0) { s_mn[warp] = mn; s_mx[warp] = mx; }
    }
    if (tid < CIN) s_sq[tid] = 0.84932180028801907f * expf(-sigma[tid]);
    for (int i = tid; i < CIN * COUT; i += TPB) W_s[i] = W[i];
    {
        const float* rb = r + (size_t)b * CIN * NG;
        #pragma unroll
        for (int h = 0; h < 2; h++) {
            int g = tid + h * 1024;
            float v[CIN];
            #pragma unroll
            for (int c = 0; c < CIN; c++) v[c] = rb[c * NG + g];
            int ebase = (g >> 5) * 4 * 32 + (g & 31);
            #pragma unroll
            for (int q = 0; q < 4; q++) {
                ulonglong2 el;
                el.x = pack2(v[4 * q + 0], v[4 * q + 1]);
                el.y = pack2(v[4 * q + 2], v[4 * q + 3]);
                s_r4[ebase + q * 32] = el;
            }
        }
    }
    __syncthreads();

    float mn = s_mn[lane];
    float mx = s_mx[lane];
    #pragma unroll
    for (int s = 16; s > 0; s >>= 1) {
        mn = fminf(mn, __shfl_xor_sync(0xFFFFFFFFu, mn, s));
        mx = fmaxf(mx, __shfl_xor_sync(0xFFFFFFFFu, mx, s));
    }
    const float xmin = mn - 0.1f;
    const float step = (mx + 0.1f - xmin) / (float)(NG - 1);

    bool uniform = true;
    #pragma unroll
    for (int c = 1; c < CIN; c++) uniform &= (s_sq[c] == s_sq[0]);

    const int o0 = blockIdx.x * TGT_BLK + tg * TGT;
    const int gbase = gr * 1024 + lane;

    unsigned long long acc[TGT][4];   // packed pairs (ch*8+2k, ch*8+2k+1)
    #pragma unroll
    for (int t = 0; t < TGT; t++)
        #pragma unroll
        for (int k = 0; k < 4; k++) acc[t][k] = 0ull;

    if (uniform) {
        const float sq    = s_sq[0];
        const float stepq = step * sq;
        const float dstep = 32.0f * stepq;

        float d[TGT];
        #pragma unroll
        for (int t = 0; t < TGT; t++)
            d[t] = fmaf((float)gbase, stepq, xmin * sq) - xt[b * NOUT + o0 + t] * sq;

        const ulonglong2* p = s_r4 + (gr * 32) * 128 + ch * 64 + lane;

        #pragma unroll 1
        for (int it = 0; it < NIT; it++) {
            unsigned long long w2[TGT];
            #pragma unroll
            for (int t = 0; t < TGT; t++) {
                float w = ex2(d[t] * -d[t]);
                d[t] += dstep;
                w2[t] = pack2(w, w);
            }
            ulonglong2 rv0 = p[0];
            ulonglong2 rv1 = p[32];
            p += 128;
            #pragma unroll
            for (int t = 0; t < TGT; t++) {
                fma2(acc[t][0], rv0.x, w2[t]);
                fma2(acc[t][1], rv0.y, w2[t]);
                fma2(acc[t][2], rv1.x, w2[t]);
                fma2(acc[t][3], rv1.y, w2[t]);
            }
        }
    } else {
        // Cold path: per-channel length scales on this warp's 8 channels,
        // then pack into the same acc[][] format for the shared tail.
        const int c0 = ch * 8;
        float kneg[8];
        #pragma unroll
        for (int c = 0; c < 8; c++) { float s = s_sq[c0 + c]; kneg[c] = -(s * s); }

        float xv[TGT];
        #pragma unroll
        for (int t = 0; t < TGT; t++) xv[t] = xt[b * NOUT + o0 + t];

        float accs[TGT][8];
        #pragma unroll
        for (int t = 0; t < TGT; t++)
            #pragma unroll
            for (int c = 0; c < 8; c++) accs[t][c] = 0.0f;

        const ulonglong2* p = s_r4 + (gr * 32) * 128 + ch * 64 + lane;
        #pragma unroll 1
        for (int it = 0; it < NIT; it++) {
            int g = gbase + it * 32;
            float gv = fmaf((float)g, step, xmin);
            ulonglong2 rv0 = p[0];
            ulonglong2 rv1 = p[32];
            p += 128;
            float rc[8];
            unpack2(rv0.x, rc[0], rc[1]);
            unpack2(rv0.y, rc[2], rc[3]);
            unpack2(rv1.x, rc[4], rc[5]);
            unpack2(rv1.y, rc[6], rc[7]);
            #pragma unroll
            for (int t = 0; t < TGT; t++) {
                float dd = gv - xv[t];
                float d2 = dd * dd;
                #pragma unroll
                for (int c = 0; c < 8; c++)
                    accs[t][c] = fmaf(rc[c], ex2(d2 * kneg[c]), accs[t][c]);
            }
        }
        #pragma unroll
        for (int t = 0; t < TGT; t++)
            #pragma unroll
            for (int k = 0; k < 4; k++)
                acc[t][k] = pack2(accs[t][2 * k], accs[t][2 * k + 1]);
    }

    // ---- Tail: 2-step butterfly + smem finish ----------------------------
    // After s=16, s=8: lane l holds the sum over lanes {l, l^8, l^16, l^24};
    // lanes 0..7 carry the 8 distinct group-sums.
    #pragma unroll
    for (int s = 16; s >= 8; s >>= 1)
        #pragma unroll
        for (int t = 0; t < TGT; t++)
            #pragma unroll
            for (int k = 0; k < 4; k++)
                add2(acc[t][k], shfl_u64(acc[t][k], s));

    if (lane < 8) {
        #pragma unroll
        for (int idx = 0; idx < 16; idx++)
            sa[warp * 128 + lane * 16 + (idx ^ (2 * lane))] = acc[idx >> 2][idx & 3];
    }
    __syncthreads();

    // 256 threads: each sums one (tg, ch, t, k) pair across 8 groups x 2
    // grid-halves (this also replaces the old cross-half combine).
    if (tid < 256) {
        int tg_ = tid >> 5, ch_ = (tid >> 4) & 1, idx = tid & 15;
        unsigned long long s = 0ull;
        #pragma unroll
        for (int gr_ = 0; gr_ < 2; gr_++) {
            int wbase = (tg_ * 4 + ch_ * 2 + gr_) * 128;
            #pragma unroll
            for (int g = 0; g < 8; g++)
                add2(s, sa[wbase + g * 16 + (idx ^ (2 * g))]);
        }
        s_z[(tg_ * 4 + (idx >> 2)) * 8 + ch_ * 4 + (idx & 3)] = s;
    }
    __syncthreads();

    // Projection: warp = output row (tg*4 + t), lane = output channel.
    {
        int row = warp;                      // 32 rows == 32 warps
        float o = bias[lane];
        #pragma unroll
        for (int ck = 0; ck < 8; ck++) {     // ck = ch*4 + k
            float lo, hi;
            unpack2(s_z[row * 8 + ck], lo, hi);
            int c = (ck >> 2) * 8 + (ck & 3) * 2;
            o = fmaf(lo, W_s[c * COUT + lane], o);
            o = fmaf(hi, W_s[(c + 1) * COUT + lane], o);
        }
        out[((size_t)b * NOUT + blockIdx.x * TGT_BLK + row) * COUT + lane] = o;
    }
}

extern "C" void kernel_launch(void* const* d_in, const int* in_sizes, int n_in,
                              void* d_out, int out_size) {
    const float* r     = (const float*)d_in[0];
    const float* xc    = (const float*)d_in[1];
    // d_in[2] = y_context — unused by the reference computation.
    const float* xt    = (const float*)d_in[3];
    const float* sigma = (const float*)d_in[4];
    const float* W     = (const float*)d_in[5];
    const float* bias  = (const float*)d_in[6];
    float* out = (float*)d_out;

    (void)in_sizes; (void)n_in; (void)out_size;

    const int smem_bytes = 4 * (NG / 32) * 32 * 16 + CIN * COUT * 4;  // 128KB + 2KB
    cudaFuncSetAttribute(conv_decoder_fused,
                         cudaFuncAttributeMaxDynamicSharedMemorySize, smem_bytes);

    dim3 grid(NOUT / TGT_BLK, NB);   // (32, 4) = 128 blocks, 1 per SM
    conv_decoder_fused<<<grid, TPB, smem_bytes>>>(r, xc, xt, sigma, W, bias, out);
}

// round 11
// speedup vs baseline: 1.8173x; 1.6440x over previous
#include <cuda_runtime.h>
#include <cuda_fp16.h>

#define NG   2048
#define NB   4
#define CIN  16
#define COUT 32
#define NCTX 256
#define NOUT 1024

#define TPB   512
#define NWARP 16
#define RSTRIDE 2056            // fp16 elems per r row (2048 + 8 pad)

__device__ __forceinline__ float ex2(float x) {
    float y;
    asm("ex2.approx.ftz.f32 %0, %1;" : "=f"(y) : "f"(x));
    return y;
}
// d = {lo, hi} packed f16x2; PTX: first source -> HIGH half.
__device__ __forceinline__ unsigned cvt_f16x2(float hi, float lo) {
    unsigned r;
    asm("cvt.rn.f16x2.f32 %0, %1, %2;" : "=r"(r) : "f"(hi), "f"(lo));
    return r;
}
__device__ __forceinline__ void mma16816(float& d0, float& d1, float& d2, float& d3,
                                         unsigned a0, unsigned a1, unsigned a2, unsigned a3,
                                         unsigned b0, unsigned b1) {
    asm("mma.sync.aligned.m16n8k16.row.col.f32.f16.f16.f32 "
        "{%0,%1,%2,%3}, {%4,%5,%6,%7}, {%8,%9}, {%0,%1,%2,%3};"
        : "+f"(d0), "+f"(d1), "+f"(d2), "+f"(d3)
        : "r"(a0), "r"(a1), "r"(a2), "r"(a3), "r"(b0), "r"(b1));
}

extern __shared__ char smem_raw[];

__global__ __launch_bounds__(TPB, 1)
void conv_decoder_mma(const float* __restrict__ r,
                      const float* __restrict__ xc,
                      const float* __restrict__ xt,
                      const float* __restrict__ sigma,
                      const float* __restrict__ W,
                      const float* __restrict__ bias,
                      float* __restrict__ out) {
    __half* r_h   = (__half*)smem_raw;                       // [CIN][RSTRIDE]
    float*  W_s   = (float*)(smem_raw + CIN * RSTRIDE * 2);  // [CIN*COUT]
    float*  z_prt = W_s + CIN * COUT;                        // [4][32][16]

    __shared__ float s_mn[NWARP], s_mx[NWARP], s_sq[CIN];

    const int b    = blockIdx.y;
    const int tid  = threadIdx.x;
    const int warp = tid >> 5;
    const int lane = tid & 31;

    // ---- Phase A: min/max scan, prescales, stage W and r(fp16) ----------
    {
        float mn = fminf(xc[tid], xc[tid + 512]);
        float mx = fmaxf(xc[tid], xc[tid + 512]);
        const float4* xt4 = (const float4*)xt;
        #pragma unroll
        for (int j = 0; j < 2; j++) {
            float4 v = xt4[j * 512 + tid];
            mn = fminf(mn, fminf(fminf(v.x, v.y), fminf(v.z, v.w)));
            mx = fmaxf(mx, fmaxf(fmaxf(v.x, v.y), fmaxf(v.z, v.w)));
        }
        #pragma unroll
        for (int s = 16; s > 0; s >>= 1) {
            mn = fminf(mn, __shfl_xor_sync(0xFFFFFFFFu, mn, s));
            mx = fmaxf(mx, __shfl_xor_sync(0xFFFFFFFFu, mx, s));
        }
        if (lane == 0) { s_mn[warp] = mn; s_mx[warp] = mx; }
    }
    if (tid < CIN) s_sq[tid] = 0.84932180028801907f * expf(-sigma[tid]);
    W_s[tid] = W[tid];                       // CIN*COUT == 512 == TPB
    {
        // row c = warp (16 warps == 16 channels); 32 lanes x 16 iters.
        int c = warp;
        const float4* rb4 = (const float4*)(r + ((size_t)b * CIN + c) * NG);
        __half* dst = r_h + c * RSTRIDE;
        #pragma unroll
        for (int it = 0; it < 16; it++) {
            float4 v = rb4[it * 32 + lane];
            unsigned p0 = cvt_f16x2(v.y, v.x);
            unsigned p1 = cvt_f16x2(v.w, v.z);
            *(uint2*)(dst + it * 128 + lane * 4) = make_uint2(p0, p1);
        }
    }
    __syncthreads();

    float mn = (lane < NWARP) ? s_mn[lane] : 1e30f;
    float mx = (lane < NWARP) ? s_mx[lane] : -1e30f;
    #pragma unroll
    for (int s = 16; s > 0; s >>= 1) {
        mn = fminf(mn, __shfl_xor_sync(0xFFFFFFFFu, mn, s));
        mx = fmaxf(mx, __shfl_xor_sync(0xFFFFFFFFu, mx, s));
    }
    const float xmin = mn - 0.1f;
    const float step = (mx + 0.1f - xmin) / (float)(NG - 1);

    bool uniform = true;
    #pragma unroll
    for (int c = 1; c < CIN; c++) uniform &= (s_sq[c] == s_sq[0]);

    if (uniform) {
        // ---- HMMA path: z(32x16) = wt(32x2048) @ rT(2048x16) -------------
        const float sq    = s_sq[0];
        const float stepq = step * sq;
        const float xminq = xmin * sq;
        const float S     = 16.0f * stepq;           // scaled stride per k-step
        const float q     = ex2(-2.0f * S * S);      // u-ratio (constant)

        const int mt = warp & 1;            // m-tile (16 targets)
        const int nt = (warp >> 1) & 1;     // n-tile (8 channels)
        const int ks = warp >> 2;           // k-split (512 grid pts)
        const int i4 = lane & 3;
        const int grp = lane >> 2;
        const int g0 = ks * 512;

        const int o_r0 = blockIdx.x * 32 + mt * 16 + grp;
        const float xq0 = xt[b * NOUT + o_r0] * sq;
        const float xq1 = xt[b * NOUT + o_r0 + 8] * sq;

        // 8 A-slots: rows {r0, r1} x cols {2i, 2i+1, 2i+8, 2i+9}
        float w[2][4], u[2][4];
        {
            const float colv[4] = {(float)(2 * i4), (float)(2 * i4 + 1),
                                   (float)(2 * i4 + 8), (float)(2 * i4 + 9)};
            #pragma unroll
            for (int cc = 0; cc < 4; cc++) {
                float pos = fmaf((float)g0 + colv[cc], stepq, xminq);
                float d0 = pos - xq0;
                float d1 = pos - xq1;
                w[0][cc] = ex2(-d0 * d0);
                w[1][cc] = ex2(-d1 * d1);
                u[0][cc] = ex2(-S * (2.0f * d0 + S));
                u[1][cc] = ex2(-S * (2.0f * d1 + S));
            }
        }

        const __half* bp = r_h + (nt * 8 + grp) * RSTRIDE + g0 + 2 * i4;
        float c0 = 0.f, c1 = 0.f, c2 = 0.f, c3 = 0.f;

        #pragma unroll 1
        for (int j = 0; j < 32; j++) {
            unsigned A0 = cvt_f16x2(w[0][1], w[0][0]);
            unsigned A1 = cvt_f16x2(w[1][1], w[1][0]);
            unsigned A2 = cvt_f16x2(w[0][3], w[0][2]);
            unsigned A3 = cvt_f16x2(w[1][3], w[1][2]);
            unsigned B0 = *(const unsigned*)bp;
            unsigned B1 = *(const unsigned*)(bp + 8);
            bp += 16;
            mma16816(c0, c1, c2, c3, A0, A1, A2, A3, B0, B1);
            #pragma unroll
            for (int rr = 0; rr < 2; rr++)
                #pragma unroll
                for (int cc = 0; cc < 4; cc++) {
                    w[rr][cc] *= u[rr][cc];
                    u[rr][cc] *= q;
                }
        }

        // Scatter this warp's 16x8 partial into its disjoint k-split slot.
        {
            float* zp = z_prt + ks * 512 + (mt * 16) * 16 + nt * 8;
            zp[grp * 16 + 2 * i4 + 0] = c0;
            zp[grp * 16 + 2 * i4 + 1] = c1;
            zp[(grp + 8) * 16 + 2 * i4 + 0] = c2;
            zp[(grp + 8) * 16 + 2 * i4 + 1] = c3;
        }
        __syncthreads();

        // Combine k-splits + project: warp = 2 rows, lane = cout.
        const float bv = bias[lane];
        #pragma unroll
        for (int rr = 0; rr < 2; rr++) {
            int row = warp * 2 + rr;
            float o = bv;
            #pragma unroll
            for (int c = 0; c < CIN; c++) {
                float zs = z_prt[row * 16 + c] + z_prt[512 + row * 16 + c]
                         + z_prt[1024 + row * 16 + c] + z_prt[1536 + row * 16 + c];
                o = fmaf(zs, W_s[c * COUT + lane], o);
            }
            out[((size_t)b * NOUT + blockIdx.x * 32 + row) * COUT + lane] = o;
        }
    } else {
        // ---- Cold path: per-channel length scales (correctness only) -----
        float kneg[CIN];
        #pragma unroll
        for (int c = 0; c < CIN; c++) { float s = s_sq[c]; kneg[c] = -(s * s); }

        int o0 = blockIdx.x * 32 + warp * 2;
        float xv0 = xt[b * NOUT + o0];
        float xv1 = xt[b * NOUT + o0 + 1];
        float a0[CIN], a1[CIN];
        #pragma unroll
        for (int c = 0; c < CIN; c++) { a0[c] = 0.f; a1[c] = 0.f; }

        const float* rb = r + (size_t)b * CIN * NG;
        #pragma unroll 1
        for (int g = lane; g < NG; g += 32) {
            float gv = fmaf((float)g, step, xmin);
            float dd0 = gv - xv0, dd1 = gv - xv1;
            float d20 = dd0 * dd0, d21 = dd1 * dd1;
            #pragma unroll
            for (int c = 0; c < CIN; c++) {
                float rv = rb[c * NG + g];
                a0[c] = fmaf(rv, ex2(d20 * kneg[c]), a0[c]);
                a1[c] = fmaf(rv, ex2(d21 * kneg[c]), a1[c]);
            }
        }
        #pragma unroll
        for (int s = 16; s > 0; s >>= 1)
            #pragma unroll
            for (int c = 0; c < CIN; c++) {
                a0[c] += __shfl_xor_sync(0xFFFFFFFFu, a0[c], s);
                a1[c] += __shfl_xor_sync(0xFFFFFFFFu, a1[c], s);
            }
        float o0v = bias[lane], o1v = bias[lane];
        #pragma unroll
        for (int c = 0; c < CIN; c++) {
            o0v = fmaf(a0[c], W_s[c * COUT + lane], o0v);
            o1v = fmaf(a1[c], W_s[c * COUT + lane], o1v);
        }
        out[((size_t)b * NOUT + o0 + 0) * COUT + lane] = o0v;
        out[((size_t)b * NOUT + o0 + 1) * COUT + lane] = o1v;
    }
}

extern "C" void kernel_launch(void* const* d_in, const int* in_sizes, int n_in,
                              void* d_out, int out_size) {
    const float* r     = (const float*)d_in[0];
    const float* xc    = (const float*)d_in[1];
    // d_in[2] = y_context — unused by the reference computation.
    const float* xt    = (const float*)d_in[3];
    const float* sigma = (const float*)d_in[4];
    const float* W     = (const float*)d_in[5];
    const float* bias  = (const float*)d_in[6];
    float* out = (float*)d_out;

    (void)in_sizes; (void)n_in; (void)out_size;

    const int smem_bytes = CIN * RSTRIDE * 2      // r fp16
                         + CIN * COUT * 4         // W
                         + 4 * 32 * 16 * 4;       // z partials
    cudaFuncSetAttribute(conv_decoder_mma,
                         cudaFuncAttributeMaxDynamicSharedMemorySize, smem_bytes);

    dim3 grid(NOUT / 32, NB);   // (32, 4) = 128 blocks
    conv_decoder_mma<<<grid, TPB, smem_bytes>>>(r, xc, xt, sigma, W, bias, out);
}

// round 12
// speedup vs baseline: 2.0311x; 1.1176x over previous
#include <cuda_runtime.h>
#include <cuda_fp16.h>

#define NG   2048
#define NB   4
#define CIN  16
#define COUT 32
#define NCTX 256
#define NOUT 1024

#define TPB   512
#define NWARP 16
#define RSTRIDE 2056            // fp16 elems per r row (2048 + 8 pad)
#define KSPLIT 8
#define KCHUNK (NG / KSPLIT)    // 256 grid points per warp
#define NITER (KCHUNK / 16)     // 16 MMA steps
#define ZROW  20                // padded z row (floats) for conflict-free STS

__device__ __forceinline__ float ex2(float x) {
    float y;
    asm("ex2.approx.ftz.f32 %0, %1;" : "=f"(y) : "f"(x));
    return y;
}
// result = {lo, hi}; PTX cvt.rn.f16x2.f32: first operand -> HIGH half.
__device__ __forceinline__ unsigned cvt_f16x2(float hi, float lo) {
    unsigned r;
    asm("cvt.rn.f16x2.f32 %0, %1, %2;" : "=r"(r) : "f"(hi), "f"(lo));
    return r;
}
__device__ __forceinline__ unsigned long long pack2(float lo, float hi) {
    unsigned long long v;
    asm("mov.b64 %0, {%1, %2};" : "=l"(v) : "f"(lo), "f"(hi));
    return v;
}
__device__ __forceinline__ void unpack2(unsigned long long v, float& lo, float& hi) {
    asm("mov.b64 {%0, %1}, %2;" : "=f"(lo), "=f"(hi) : "l"(v));
}
__device__ __forceinline__ void mul2(unsigned long long& d, unsigned long long a) {
    asm("mul.rn.f32x2 %0, %0, %1;" : "+l"(d) : "l"(a));
}
__device__ __forceinline__ void mma16816(float& d0, float& d1, float& d2, float& d3,
                                         unsigned a0, unsigned a1, unsigned a2, unsigned a3,
                                         unsigned b0, unsigned b1) {
    asm("mma.sync.aligned.m16n8k16.row.col.f32.f16.f16.f32 "
        "{%0,%1,%2,%3}, {%4,%5,%6,%7}, {%8,%9}, {%0,%1,%2,%3};"
        : "+f"(d0), "+f"(d1), "+f"(d2), "+f"(d3)
        : "r"(a0), "r"(a1), "r"(a2), "r"(a3), "r"(b0), "r"(b1));
}

extern __shared__ char smem_raw[];

__global__ __launch_bounds__(TPB, 1)
void conv_decoder_mma(const float* __restrict__ r,
                      const float* __restrict__ xc,
                      const float* __restrict__ xt,
                      const float* __restrict__ sigma,
                      const float* __restrict__ W,
                      const float* __restrict__ bias,
                      float* __restrict__ out) {
    __half* r_h   = (__half*)smem_raw;                       // [CIN][RSTRIDE]
    float*  W_s   = (float*)(smem_raw + CIN * RSTRIDE * 2);  // [CIN*COUT]
    float*  z_prt = W_s + CIN * COUT;                        // [KSPLIT][32][ZROW]
    float*  s_z   = z_prt + KSPLIT * 32 * ZROW;              // [32][CIN]

    __shared__ float s_mn[NWARP], s_mx[NWARP], s_sq[CIN];

    const int b    = blockIdx.y;
    const int tid  = threadIdx.x;
    const int warp = tid >> 5;
    const int lane = tid & 31;

    // ---- Phase A: min/max scan, prescales, stage W and r(fp16) ----------
    {
        float mn = fminf(xc[tid], xc[tid + 512]);
        float mx = fmaxf(xc[tid], xc[tid + 512]);
        const float4* xt4 = (const float4*)xt;
        #pragma unroll
        for (int j = 0; j < 2; j++) {
            float4 v = xt4[j * 512 + tid];
            mn = fminf(mn, fminf(fminf(v.x, v.y), fminf(v.z, v.w)));
            mx = fmaxf(mx, fmaxf(fmaxf(v.x, v.y), fmaxf(v.z, v.w)));
        }
        #pragma unroll
        for (int s = 16; s > 0; s >>= 1) {
            mn = fminf(mn, __shfl_xor_sync(0xFFFFFFFFu, mn, s));
            mx = fmaxf(mx, __shfl_xor_sync(0xFFFFFFFFu, mx, s));
        }
        if (lane == 0) { s_mn[warp] = mn; s_mx[warp] = mx; }
    }
    if (tid < CIN) s_sq[tid] = 0.84932180028801907f * expf(-sigma[tid]);
    W_s[tid] = W[tid];                       // CIN*COUT == 512 == TPB
    {
        int c = warp;                        // warp stages channel c
        const float4* rb4 = (const float4*)(r + ((size_t)b * CIN + c) * NG);
        __half* dst = r_h + c * RSTRIDE;
        #pragma unroll
        for (int it = 0; it < 16; it++) {
            float4 v = rb4[it * 32 + lane];
            unsigned p0 = cvt_f16x2(v.y, v.x);
            unsigned p1 = cvt_f16x2(v.w, v.z);
            *(uint2*)(dst + it * 128 + lane * 4) = make_uint2(p0, p1);
        }
    }
    __syncthreads();

    float mn = (lane < NWARP) ? s_mn[lane] : 1e30f;
    float mx = (lane < NWARP) ? s_mx[lane] : -1e30f;
    #pragma unroll
    for (int s = 16; s > 0; s >>= 1) {
        mn = fminf(mn, __shfl_xor_sync(0xFFFFFFFFu, mn, s));
        mx = fmaxf(mx, __shfl_xor_sync(0xFFFFFFFFu, mx, s));
    }
    const float xmin = mn - 0.1f;
    const float step = (mx + 0.1f - xmin) / (float)(NG - 1);

    bool uniform = true;
    #pragma unroll
    for (int c = 1; c < CIN; c++) uniform &= (s_sq[c] == s_sq[0]);

    if (uniform) {
        // ---- HMMA: z(32x16) = wt(32x2048) @ rT(2048x16) ------------------
        // warp = (mt, ks): A generated ONCE, used for both channel n-tiles.
        const float sq    = s_sq[0];
        const float stepq = step * sq;
        const float xminq = xmin * sq;
        const float S     = 16.0f * stepq;          // scaled k-step stride
        const unsigned long long qq = [&]{ float q = ex2(-2.0f * S * S);
                                           return pack2(q, q); }();

        const int mt  = warp & 1;           // m-tile (16 targets)
        const int ks  = warp >> 1;          // k-split 0..7
        const int i4  = lane & 3;
        const int grp = lane >> 2;
        const int g0  = ks * KCHUNK;

        const int o_r0 = blockIdx.x * 32 + mt * 16 + grp;
        const float xq0 = xt[b * NOUT + o_r0] * sq;
        const float xq1 = xt[b * NOUT + o_r0 + 8] * sq;

        // Packed weight/update pairs: pw[rr][p] = {w(col_p), w(col_p+1)},
        // col_0 = 2*i4, col_1 = 2*i4+8.
        unsigned long long pw[2][2], pu[2][2];
        #pragma unroll
        for (int p = 0; p < 2; p++) {
            float col = (float)(2 * i4 + 8 * p);
            float pos0 = fmaf((float)g0 + col, stepq, xminq);
            float pos1 = pos0 + stepq;
            float dA0 = pos0 - xq0, dA1 = pos1 - xq0;
            float dB0 = pos0 - xq1, dB1 = pos1 - xq1;
            pw[0][p] = pack2(ex2(-dA0 * dA0), ex2(-dA1 * dA1));
            pw[1][p] = pack2(ex2(-dB0 * dB0), ex2(-dB1 * dB1));
            pu[0][p] = pack2(ex2(-S * (2.0f * dA0 + S)), ex2(-S * (2.0f * dA1 + S)));
            pu[1][p] = pack2(ex2(-S * (2.0f * dB0 + S)), ex2(-S * (2.0f * dB1 + S)));
        }

        const __half* bp0 = r_h + grp * RSTRIDE + g0 + 2 * i4;        // ch 0-7
        const __half* bp1 = bp0 + 8 * RSTRIDE;                        // ch 8-15
        float c0 = 0.f, c1 = 0.f, c2 = 0.f, c3 = 0.f;
        float c4 = 0.f, c5 = 0.f, c6 = 0.f, c7 = 0.f;

        #pragma unroll 1
        for (int j = 0; j < NITER; j++) {
            float lo, hi;
            unpack2(pw[0][0], lo, hi); unsigned A0 = cvt_f16x2(hi, lo);
            unpack2(pw[1][0], lo, hi); unsigned A1 = cvt_f16x2(hi, lo);
            unpack2(pw[0][1], lo, hi); unsigned A2 = cvt_f16x2(hi, lo);
            unpack2(pw[1][1], lo, hi); unsigned A3 = cvt_f16x2(hi, lo);

            unsigned B00 = *(const unsigned*)bp0;
            unsigned B01 = *(const unsigned*)(bp0 + 8);
            unsigned B10 = *(const unsigned*)bp1;
            unsigned B11 = *(const unsigned*)(bp1 + 8);
            bp0 += 16; bp1 += 16;

            mma16816(c0, c1, c2, c3, A0, A1, A2, A3, B00, B01);
            mma16816(c4, c5, c6, c7, A0, A1, A2, A3, B10, B11);

            #pragma unroll
            for (int rr = 0; rr < 2; rr++)
                #pragma unroll
                for (int p = 0; p < 2; p++) {
                    mul2(pw[rr][p], pu[rr][p]);
                    mul2(pu[rr][p], qq);
                }
        }

        // Scatter 16x16 partial into this warp's k-split slot (padded rows).
        {
            float* zp = z_prt + ks * (32 * ZROW) + (mt * 16) * ZROW;
            zp[grp * ZROW + 2 * i4 + 0] = c0;
            zp[grp * ZROW + 2 * i4 + 1] = c1;
            zp[(grp + 8) * ZROW + 2 * i4 + 0] = c2;
            zp[(grp + 8) * ZROW + 2 * i4 + 1] = c3;
            zp[grp * ZROW + 8 + 2 * i4 + 0] = c4;
            zp[grp * ZROW + 8 + 2 * i4 + 1] = c5;
            zp[(grp + 8) * ZROW + 8 + 2 * i4 + 0] = c6;
            zp[(grp + 8) * ZROW + 8 + 2 * i4 + 1] = c7;
        }
        __syncthreads();

        // Combine k-splits: thread = (row, cin); 8 loads + 7 adds.
        {
            int row = tid >> 4, c = tid & 15;
            float s = 0.f;
            #pragma unroll
            for (int k = 0; k < KSPLIT; k++)
                s += z_prt[k * (32 * ZROW) + row * ZROW + c];
            s_z[row * CIN + c] = s;
        }
        __syncthreads();

        // Projection: warp = 2 rows, lane = cout.
        const float bv = bias[lane];
        #pragma unroll
        for (int rr = 0; rr < 2; rr++) {
            int row = warp * 2 + rr;
            float o = bv;
            #pragma unroll
            for (int c = 0; c < CIN; c++)
                o = fmaf(s_z[row * CIN + c], W_s[c * COUT + lane], o);
            out[((size_t)b * NOUT + blockIdx.x * 32 + row) * COUT + lane] = o;
        }
    } else {
        // ---- Cold path: per-channel length scales (correctness only) -----
        float kneg[CIN];
        #pragma unroll
        for (int c = 0; c < CIN; c++) { float s = s_sq[c]; kneg[c] = -(s * s); }

        int o0 = blockIdx.x * 32 + warp * 2;
        float xv0 = xt[b * NOUT + o0];
        float xv1 = xt[b * NOUT + o0 + 1];
        float a0[CIN], a1[CIN];
        #pragma unroll
        for (int c = 0; c < CIN; c++) { a0[c] = 0.f; a1[c] = 0.f; }

        const float* rb = r + (size_t)b * CIN * NG;
        #pragma unroll 1
        for (int g = lane; g < NG; g += 32) {
            float gv = fmaf((float)g, step, xmin);
            float dd0 = gv - xv0, dd1 = gv - xv1;
            float d20 = dd0 * dd0, d21 = dd1 * dd1;
            #pragma unroll
            for (int c = 0; c < CIN; c++) {
                float rv = rb[c * NG + g];
                a0[c] = fmaf(rv, ex2(d20 * kneg[c]), a0[c]);
                a1[c] = fmaf(rv, ex2(d21 * kneg[c]), a1[c]);
            }
        }
        #pragma unroll
        for (int s = 16; s > 0; s >>= 1)
            #pragma unroll
            for (int c = 0; c < CIN; c++) {
                a0[c] += __shfl_xor_sync(0xFFFFFFFFu, a0[c], s);
                a1[c] += __shfl_xor_sync(0xFFFFFFFFu, a1[c], s);
            }
        float o0v = bias[lane], o1v = bias[lane];
        #pragma unroll
        for (int c = 0; c < CIN; c++) {
            o0v = fmaf(a0[c], W_s[c * COUT + lane], o0v);
            o1v = fmaf(a1[c], W_s[c * COUT + lane], o1v);
        }
        out[((size_t)b * NOUT + o0 + 0) * COUT + lane] = o0v;
        out[((size_t)b * NOUT + o0 + 1) * COUT + lane] = o1v;
    }
}

extern "C" void kernel_launch(void* const* d_in, const int* in_sizes, int n_in,
                              void* d_out, int out_size) {
    const float* r     = (const float*)d_in[0];
    const float* xc    = (const float*)d_in[1];
    // d_in[2] = y_context — unused by the reference computation.
    const float* xt    = (const float*)d_in[3];
    const float* sigma = (const float*)d_in[4];
    const float* W     = (const float*)d_in[5];
    const float* bias  = (const float*)d_in[6];
    float* out = (float*)d_out;

    (void)in_sizes; (void)n_in; (void)out_size;

    const int smem_bytes = CIN * RSTRIDE * 2          // r fp16
                         + CIN * COUT * 4             // W
                         + KSPLIT * 32 * ZROW * 4     // z partials (padded)
                         + 32 * CIN * 4;              // reduced z
    cudaFuncSetAttribute(conv_decoder_mma,
                         cudaFuncAttributeMaxDynamicSharedMemorySize, smem_bytes);

    dim3 grid(NOUT / 32, NB);   // (32, 4) = 128 blocks
    conv_decoder_mma<<<grid, TPB, smem_bytes>>>(r, xc, xt, sigma, W, bias, out);
}